// round 9
// baseline (speedup 1.0000x reference)
#include <cuda_runtime.h>

#define Nn 50000
#define Rr 16
#define Hh 32
#define Ll 8
#define Ee 1600000

// Scratch (static __device__ arrays: allocation-free per harness rules)
__device__ __align__(16) int   g_cnt[Rr * Nn];       // per-(relation,dst) edge counts
__device__ __align__(16) float g_enorm[Ee];          // per-edge 1/deg_r(dst) (layer1 writes)
__device__ __align__(16) float g_h1[Nn * Hh];        // layer-1 aggregation
__device__ __align__(16) float g_T[Rr * Nn * Ll];    // T[r,n,l] = (h1[n,:] @ W2[r])[l]

// Vector reduction: 4x fp32 add in one L2 atomic op (sm_90+)
__device__ __forceinline__ void red_add_v4(float* p, float4 v) {
    asm volatile("red.global.add.v4.f32 [%0], {%1,%2,%3,%4};"
                 :: "l"(p), "f"(v.x), "f"(v.y), "f"(v.z), "f"(v.w)
                 : "memory");
}

// L1-bypassing float4 load (cache-global: no L1 allocate, keeps L2)
__device__ __forceinline__ float4 ldcg_f4(const float4* p) {
    float4 v;
    asm("ld.global.cg.v4.f32 {%0,%1,%2,%3}, [%4];"
        : "=f"(v.x), "=f"(v.y), "=f"(v.z), "=f"(v.w) : "l"(p));
    return v;
}

// Packed f32x2 FMA (sm_103a): acc = a * b + acc, two fp32 lanes per op
__device__ __forceinline__ void fma_f32x2(unsigned long long& acc,
                                          unsigned long long a,
                                          unsigned long long b) {
    asm("fma.rn.f32x2 %0, %1, %2, %0;" : "+l"(acc) : "l"(a), "l"(b));
}
__device__ __forceinline__ unsigned long long pack_f32x2(float lo, float hi) {
    unsigned long long r;
    asm("mov.b64 %0, {%1, %2};" : "=l"(r) : "f"(lo), "f"(hi));
    return r;
}
__device__ __forceinline__ void unpack_f32x2(unsigned long long v, float& lo, float& hi) {
    asm("mov.b64 {%0, %1}, %2;" : "=f"(lo), "=f"(hi) : "l"(v));
}

// ---------------------------------------------------------------------------
// Zero accumulators (g_cnt, g_h1). out is initialized by k_T.
// ---------------------------------------------------------------------------
__global__ void k_zero() {
    int i = blockIdx.x * blockDim.x + threadIdx.x;
    int stride = gridDim.x * blockDim.x;
    float4 z = make_float4(0.f, 0.f, 0.f, 0.f);
    int4* c4 = (int4*)g_cnt;
    float4* h4 = (float4*)g_h1;
    for (int j = i; j < (Rr * Nn) / 4; j += stride) c4[j] = make_int4(0, 0, 0, 0);
    for (int j = i; j < (Nn * Hh) / 4; j += stride) h4[j] = z;
}

// ---------------------------------------------------------------------------
// Per-(relation,dst) edge counts. 8 edges per thread (MLP=8).
// ---------------------------------------------------------------------------
__global__ void k_count(const int* __restrict__ et, const int* __restrict__ dst) {
    int t = blockIdx.x * blockDim.x + threadIdx.x;
    if (t >= Ee / 8) return;
    int e0 = t * 8;
    int4 da = *(const int4*)(dst + e0);
    int4 db = *(const int4*)(dst + e0 + 4);
    int4 ra = *(const int4*)(et + e0);
    int4 rb = *(const int4*)(et + e0 + 4);
    atomicAdd(&g_cnt[ra.x * Nn + da.x], 1);
    atomicAdd(&g_cnt[ra.y * Nn + da.y], 1);
    atomicAdd(&g_cnt[ra.z * Nn + da.z], 1);
    atomicAdd(&g_cnt[ra.w * Nn + da.w], 1);
    atomicAdd(&g_cnt[rb.x * Nn + db.x], 1);
    atomicAdd(&g_cnt[rb.y * Nn + db.y], 1);
    atomicAdd(&g_cnt[rb.z * Nn + db.z], 1);
    atomicAdd(&g_cnt[rb.w * Nn + db.w], 1);
}

// ---------------------------------------------------------------------------
// Layer 1: 8 threads per edge (quarter-row each), 4 edges per thread.
//   norm = 1/max(cnt[r*N+d],1)   (inline gather, broadcast across 8 lanes)
//   g_h1[dst, q*4..] += W1[r, src, q*4..] * norm
// Lane q==0 stores the 4 edge-norms to g_enorm for layer2 reuse.
// W1 loads bypass L1 allocation (.cg) — avg reuse ~2 random touches.
// ---------------------------------------------------------------------------
__global__ void k_layer1(const int* __restrict__ src, const int* __restrict__ dst,
                         const int* __restrict__ et, const float* __restrict__ W1) {
    int g = blockIdx.x * blockDim.x + threadIdx.x;
    int grp = g >> 3;        // which edge-quad
    int q = g & 7;           // which quarter of the 32-wide row
    if (grp >= Ee / 4) return;
    int e0 = grp * 4;

    int4 s4 = *(const int4*)(src + e0);
    int4 d4 = *(const int4*)(dst + e0);
    int4 r4 = *(const int4*)(et + e0);
    int ss[4] = {s4.x, s4.y, s4.z, s4.w};
    int dd[4] = {d4.x, d4.y, d4.z, d4.w};
    int rr[4] = {r4.x, r4.y, r4.z, r4.w};

    float  nn[4];
    float4 ww[4];
#pragma unroll
    for (int k = 0; k < 4; k++) {
        nn[k] = 1.0f / fmaxf((float)g_cnt[rr[k] * Nn + dd[k]], 1.0f);
        ww[k] = ldcg_f4((const float4*)(W1 + (rr[k] * Nn + ss[k]) * Hh + q * 4));
    }
    if (q == 0) {
        *(float4*)(g_enorm + e0) = make_float4(nn[0], nn[1], nn[2], nn[3]);
    }
#pragma unroll
    for (int k = 0; k < 4; k++) {
        float4 v = make_float4(ww[k].x * nn[k], ww[k].y * nn[k],
                               ww[k].z * nn[k], ww[k].w * nn[k]);
        red_add_v4(&g_h1[dd[k] * Hh + q * 4], v);
    }
}

// ---------------------------------------------------------------------------
// Fused:  h = relu(agg1 + root1 + b1)            (registers only)
//         out_base[n,l] = (h @ root2)[l] + b2    (layer2 REDs onto this)
//         T[r,n,l] = sum_h h[n,h] * W2[r,h,l]
// Block = 64 nodes x 4 l-pair threads. f32x2 packed FMAs.
// ---------------------------------------------------------------------------
__global__ void k_T(const float* __restrict__ W2, const float* __restrict__ root1,
                    const float* __restrict__ b1, const float* __restrict__ root2,
                    const float* __restrict__ b2, float* __restrict__ out) {
    __shared__ float sW[Rr * Hh * Ll];   // [r][h][l], 16KB
    __shared__ float sR[Hh * Ll];        // root2 [h][l], 1KB
    __shared__ float sB1[Hh];
    __shared__ float sB2[Ll];
    for (int i = threadIdx.x; i < Rr * Hh * Ll; i += blockDim.x) sW[i] = W2[i];
    for (int i = threadIdx.x; i < Hh * Ll; i += blockDim.x) sR[i] = root2[i];
    if (threadIdx.x < Hh) sB1[threadIdx.x] = b1[threadIdx.x];
    if (threadIdx.x < Ll) sB2[threadIdx.x] = b2[threadIdx.x];
    __syncthreads();

    int n = blockIdx.x * 64 + (threadIdx.x >> 2);
    int lp = threadIdx.x & 3;            // l-pair index: l = 2*lp, 2*lp+1
    if (n >= Nn) return;

    // relu(agg + root1 + b1) -> h[32] (registers; g_h1 not needed afterwards)
    float h[Hh];
    const float4* ap = (const float4*)(g_h1 + n * Hh);
    const float4* rp = (const float4*)(root1 + n * Hh);
#pragma unroll
    for (int j = 0; j < 8; j++) {
        float4 av = ap[j];
        float4 rv = rp[j];
        h[j * 4 + 0] = fmaxf(av.x + rv.x + sB1[j * 4 + 0], 0.0f);
        h[j * 4 + 1] = fmaxf(av.y + rv.y + sB1[j * 4 + 1], 0.0f);
        h[j * 4 + 2] = fmaxf(av.z + rv.z + sB1[j * 4 + 2], 0.0f);
        h[j * 4 + 3] = fmaxf(av.w + rv.w + sB1[j * 4 + 3], 0.0f);
    }

    // out base: y(l=2lp, 2lp+1) = h @ root2 + b2
    {
        unsigned long long yacc = pack_f32x2(sB2[lp * 2], sB2[lp * 2 + 1]);
#pragma unroll
        for (int hh = 0; hh < Hh; hh++) {
            float2 rv = *(const float2*)(sR + hh * Ll + lp * 2);
            fma_f32x2(yacc, pack_f32x2(h[hh], h[hh]), pack_f32x2(rv.x, rv.y));
        }
        float lo, hi;
        unpack_f32x2(yacc, lo, hi);
        *(float2*)(out + n * Ll + lp * 2) = make_float2(lo, hi);
    }

    unsigned long long acc[Rr];
#pragma unroll
    for (int r = 0; r < Rr; r++) acc[r] = pack_f32x2(0.0f, 0.0f);

#pragma unroll
    for (int hh = 0; hh < Hh; hh++) {
        unsigned long long hv = pack_f32x2(h[hh], h[hh]);
#pragma unroll
        for (int r = 0; r < Rr; r++) {
            float2 w = *(const float2*)(sW + (r * Hh + hh) * Ll + lp * 2);
            fma_f32x2(acc[r], hv, pack_f32x2(w.x, w.y));
        }
    }
#pragma unroll
    for (int r = 0; r < Rr; r++) {
        float lo, hi;
        unpack_f32x2(acc[r], lo, hi);
        *(float2*)(g_T + (r * Nn + n) * Ll + lp * 2) = make_float2(lo, hi);
    }
}

// ---------------------------------------------------------------------------
// Layer 2 edge pass: 2 threads per edge (half-row each), 8 edges per thread.
//   out[dst, half*4..] += enorm[e] * T[r, src, half*4..]
// T gathers bypass L1 allocation (.cg) — 25.6MB, L2-resident, no L1 reuse.
// ---------------------------------------------------------------------------
__global__ void k_layer2(const int* __restrict__ src, const int* __restrict__ dst,
                         const int* __restrict__ et, float* __restrict__ out) {
    int g = blockIdx.x * blockDim.x + threadIdx.x;
    int oct = g >> 1;
    int half = g & 1;
    if (oct >= Ee / 8) return;
    int e0 = oct * 8;

    int4 sa = *(const int4*)(src + e0);
    int4 sb = *(const int4*)(src + e0 + 4);
    int4 da = *(const int4*)(dst + e0);
    int4 db = *(const int4*)(dst + e0 + 4);
    int4 ra = *(const int4*)(et + e0);
    int4 rb = *(const int4*)(et + e0 + 4);
    float4 na = *(const float4*)(g_enorm + e0);
    float4 nb = *(const float4*)(g_enorm + e0 + 4);
    int ss[8] = {sa.x, sa.y, sa.z, sa.w, sb.x, sb.y, sb.z, sb.w};
    int dd[8] = {da.x, da.y, da.z, da.w, db.x, db.y, db.z, db.w};
    int rr[8] = {ra.x, ra.y, ra.z, ra.w, rb.x, rb.y, rb.z, rb.w};
    float nn[8] = {na.x, na.y, na.z, na.w, nb.x, nb.y, nb.z, nb.w};

    float4 tv[8];
#pragma unroll
    for (int k = 0; k < 8; k++) {
        tv[k] = ldcg_f4((const float4*)(g_T + (rr[k] * Nn + ss[k]) * Ll + half * 4));
    }
#pragma unroll
    for (int k = 0; k < 8; k++) {
        float4 v = make_float4(tv[k].x * nn[k], tv[k].y * nn[k],
                               tv[k].z * nn[k], tv[k].w * nn[k]);
        red_add_v4(&out[dd[k] * Ll + half * 4], v);
    }
}

// ---------------------------------------------------------------------------
// Final: out = sigmoid(out), elementwise
// ---------------------------------------------------------------------------
__global__ void k_final(float* __restrict__ out) {
    int i = blockIdx.x * blockDim.x + threadIdx.x;
    if (i >= (Nn * Ll) / 4) return;
    float4 v = ((const float4*)out)[i];
    v.x = 1.0f / (1.0f + expf(-v.x));
    v.y = 1.0f / (1.0f + expf(-v.y));
    v.z = 1.0f / (1.0f + expf(-v.z));
    v.w = 1.0f / (1.0f + expf(-v.w));
    ((float4*)out)[i] = v;
}

// ---------------------------------------------------------------------------
extern "C" void kernel_launch(void* const* d_in, const int* in_sizes, int n_in,
                              void* d_out, int out_size) {
    const int* ei    = (const int*)d_in[0];    // edge_index [2, E]
    const int* et    = (const int*)d_in[1];    // edge_type  [E]
    const float* W1  = (const float*)d_in[2];  // [R, N, H]
    const float* rt1 = (const float*)d_in[3];  // [N, H]
    const float* b1  = (const float*)d_in[4];  // [H]
    const float* W2  = (const float*)d_in[5];  // [R, H, L]
    const float* rt2 = (const float*)d_in[6];  // [H, L]
    const float* b2  = (const float*)d_in[7];  // [L]
    float* out = (float*)d_out;                // [N, L]

    const int* src = ei;
    const int* dst = ei + Ee;

    k_zero<<<1024, 256>>>();
    k_count<<<(Ee / 8 + 255) / 256, 256>>>(et, dst);
    k_layer1<<<(Ee / 4) * 8 / 256, 256>>>(src, dst, et, W1);     // 8 thr/edge, 4 edges/thr
    k_T<<<(Nn + 63) / 64, 256>>>(W2, rt1, b1, rt2, b2, out);     // relu + T + out-base
    k_layer2<<<((Ee / 8) * 2 + 255) / 256, 256>>>(src, dst, et, out); // 2 thr/edge, 8 edges/thr
    k_final<<<((Nn * Ll) / 4 + 255) / 256, 256>>>(out);
}

// round 10
// speedup vs baseline: 1.0650x; 1.0650x over previous
#include <cuda_runtime.h>

#define Nn 50000
#define Rr 16
#define Hh 32
#define Ll 8
#define Ee 1600000

// Scratch (static __device__ arrays: allocation-free per harness rules)
__device__ __align__(16) int   g_cnt[Rr * Nn];       // per-(relation,dst) edge counts
__device__ __align__(16) float g_enorm[Ee];          // per-edge 1/deg_r(dst) (layer1 writes)
__device__ __align__(16) float g_h1[Nn * Hh];        // layer-1 aggregation
__device__ __align__(16) float g_T[Nn * Rr * Ll];    // T[n][r][l] = (h1[n,:] @ W2[r])[l]

// Vector reduction: 4x fp32 add in one L2 atomic op (sm_90+)
__device__ __forceinline__ void red_add_v4(float* p, float4 v) {
    asm volatile("red.global.add.v4.f32 [%0], {%1,%2,%3,%4};"
                 :: "l"(p), "f"(v.x), "f"(v.y), "f"(v.z), "f"(v.w)
                 : "memory");
}

// ---------------------------------------------------------------------------
// Zero accumulators (g_cnt, g_h1). out is initialized by k_T.
// ---------------------------------------------------------------------------
__global__ void k_zero() {
    int i = blockIdx.x * blockDim.x + threadIdx.x;
    int stride = gridDim.x * blockDim.x;
    float4 z = make_float4(0.f, 0.f, 0.f, 0.f);
    int4* c4 = (int4*)g_cnt;
    float4* h4 = (float4*)g_h1;
    for (int j = i; j < (Rr * Nn) / 4; j += stride) c4[j] = make_int4(0, 0, 0, 0);
    for (int j = i; j < (Nn * Hh) / 4; j += stride) h4[j] = z;
}

// ---------------------------------------------------------------------------
// Per-(relation,dst) edge counts. 8 edges per thread (MLP=8).
// ---------------------------------------------------------------------------
__global__ void k_count(const int* __restrict__ et, const int* __restrict__ dst) {
    int t = blockIdx.x * blockDim.x + threadIdx.x;
    if (t >= Ee / 8) return;
    int e0 = t * 8;
    int4 da = *(const int4*)(dst + e0);
    int4 db = *(const int4*)(dst + e0 + 4);
    int4 ra = *(const int4*)(et + e0);
    int4 rb = *(const int4*)(et + e0 + 4);
    atomicAdd(&g_cnt[ra.x * Nn + da.x], 1);
    atomicAdd(&g_cnt[ra.y * Nn + da.y], 1);
    atomicAdd(&g_cnt[ra.z * Nn + da.z], 1);
    atomicAdd(&g_cnt[ra.w * Nn + da.w], 1);
    atomicAdd(&g_cnt[rb.x * Nn + db.x], 1);
    atomicAdd(&g_cnt[rb.y * Nn + db.y], 1);
    atomicAdd(&g_cnt[rb.z * Nn + db.z], 1);
    atomicAdd(&g_cnt[rb.w * Nn + db.w], 1);
}

// ---------------------------------------------------------------------------
// Layer 1: 8 threads per edge (quarter-row each), 4 edges per thread.
//   norm = 1/max(cnt[r*N+d],1)   (inline gather)
//   g_h1[dst, q*4..] += W1[r, src, q*4..] * norm
// Lane q==0 stores the 4 edge-norms to g_enorm for layer2 reuse.
// ---------------------------------------------------------------------------
__global__ void k_layer1(const int* __restrict__ src, const int* __restrict__ dst,
                         const int* __restrict__ et, const float* __restrict__ W1) {
    int g = blockIdx.x * blockDim.x + threadIdx.x;
    int grp = g >> 3;        // which edge-quad
    int q = g & 7;           // which quarter of the 32-wide row
    if (grp >= Ee / 4) return;
    int e0 = grp * 4;

    int4 s4 = *(const int4*)(src + e0);
    int4 d4 = *(const int4*)(dst + e0);
    int4 r4 = *(const int4*)(et + e0);
    int ss[4] = {s4.x, s4.y, s4.z, s4.w};
    int dd[4] = {d4.x, d4.y, d4.z, d4.w};
    int rr[4] = {r4.x, r4.y, r4.z, r4.w};

    float  nn[4];
    float4 ww[4];
#pragma unroll
    for (int k = 0; k < 4; k++) {
        nn[k] = 1.0f / fmaxf((float)__ldg(&g_cnt[rr[k] * Nn + dd[k]]), 1.0f);
        ww[k] = *(const float4*)(W1 + (rr[k] * Nn + ss[k]) * Hh + q * 4);
    }
    if (q == 0) {
        *(float4*)(g_enorm + e0) = make_float4(nn[0], nn[1], nn[2], nn[3]);
    }
#pragma unroll
    for (int k = 0; k < 4; k++) {
        float4 v = make_float4(ww[k].x * nn[k], ww[k].y * nn[k],
                               ww[k].z * nn[k], ww[k].w * nn[k]);
        red_add_v4(&g_h1[dd[k] * Hh + q * 4], v);
    }
}

// ---------------------------------------------------------------------------
// Fused k_T (register-weight GEMM):
//   h = relu(agg + root1 + b1)                       (staged in 4KB shared/tile)
//   T[n][r][l] = sum_h h[n,h] * W2[r,h,l]            (w slice in 64 REGISTERS)
//   out[n,l]   = (h @ root2)[l] + b2[l]              (base for layer2 REDs)
// Block = 256 thr: 4 groups x 64 (r,lp) threads; tile = 32 nodes, 8 nodes/group.
// Per node per thread: 8 broadcast LDS.128 + 64 FFMA  -> FMA-pipe bound.
// ---------------------------------------------------------------------------
__global__ void k_T(const float* __restrict__ W2, const float* __restrict__ root1,
                    const float* __restrict__ b1, const float* __restrict__ root2,
                    const float* __restrict__ b2, float* __restrict__ out) {
    __shared__ float4 sH[256];           // 32 nodes x 32 h  (sH[node*8+j])
    __shared__ float  sR[Hh * Ll];       // root2 [h][l]

    int tid = threadIdx.x;
    for (int i = tid; i < Hh * Ll; i += 256) sR[i] = root2[i];

    // W2 slice into registers: thread owns (r, lp) -> W2[r][0..31][lp*2, lp*2+1]
    int r  = (tid >> 2) & 15;
    int lp = tid & 3;
    int grp = tid >> 6;                  // 4 node-groups
    float2 w[Hh];
#pragma unroll
    for (int hh = 0; hh < Hh; hh++)
        w[hh] = *(const float2*)(W2 + (r * Hh + hh) * Ll + lp * 2);

    // Phase A: stage relu(agg + root1 + b1) for 32 nodes
    int tile = blockIdx.x;
    int gidx = tile * 1024 + tid * 4;    // float index into [n][h] arrays
    float4 hv = make_float4(0.f, 0.f, 0.f, 0.f);
    if (gidx < Nn * Hh) {
        float4 av = *(const float4*)(g_h1 + gidx);
        float4 rv = *(const float4*)(root1 + gidx);
        int h0 = (tid & 7) * 4;
        hv.x = fmaxf(av.x + rv.x + __ldg(b1 + h0 + 0), 0.0f);
        hv.y = fmaxf(av.y + rv.y + __ldg(b1 + h0 + 1), 0.0f);
        hv.z = fmaxf(av.z + rv.z + __ldg(b1 + h0 + 2), 0.0f);
        hv.w = fmaxf(av.w + rv.w + __ldg(b1 + h0 + 3), 0.0f);
    }
    sH[tid] = hv;
    __syncthreads();

    // Out-base: thread = (node_in_tile, l)
    {
        int node = tid >> 3;
        int l = tid & 7;
        int n = tile * 32 + node;
        if (n < Nn) {
            const float* sHf = (const float*)sH;
            float y = __ldg(b2 + l);
#pragma unroll
            for (int hh = 0; hh < Hh; hh++)
                y += sHf[node * Hh + hh] * sR[hh * Ll + l];
            out[n * Ll + l] = y;
        }
    }

    // Main: each (grp, r, lp) thread handles 8 nodes
#pragma unroll
    for (int i = 0; i < 8; i++) {
        int ni = grp * 8 + i;
        int n = tile * 32 + ni;
        if (n >= Nn) break;
        float a0 = 0.0f, a1 = 0.0f;
#pragma unroll
        for (int j = 0; j < 8; j++) {
            float4 h4 = sH[ni * 8 + j];          // broadcast LDS.128
            a0 += h4.x * w[j*4+0].x + h4.y * w[j*4+1].x
                + h4.z * w[j*4+2].x + h4.w * w[j*4+3].x;
            a1 += h4.x * w[j*4+0].y + h4.y * w[j*4+1].y
                + h4.z * w[j*4+2].y + h4.w * w[j*4+3].y;
        }
        *(float2*)(g_T + (n * Rr + r) * Ll + lp * 2) = make_float2(a0, a1);
    }
}

// ---------------------------------------------------------------------------
// Layer 2 edge pass: 2 threads per edge (half-row each), 8 edges per thread.
//   out[dst, half*4..] += enorm[e] * T[src][r][half*4..]
// ---------------------------------------------------------------------------
__global__ void k_layer2(const int* __restrict__ src, const int* __restrict__ dst,
                         const int* __restrict__ et, float* __restrict__ out) {
    int g = blockIdx.x * blockDim.x + threadIdx.x;
    int oct = g >> 1;
    int half = g & 1;
    if (oct >= Ee / 8) return;
    int e0 = oct * 8;

    int4 sa = *(const int4*)(src + e0);
    int4 sb = *(const int4*)(src + e0 + 4);
    int4 da = *(const int4*)(dst + e0);
    int4 db = *(const int4*)(dst + e0 + 4);
    int4 ra = *(const int4*)(et + e0);
    int4 rb = *(const int4*)(et + e0 + 4);
    float4 na = *(const float4*)(g_enorm + e0);
    float4 nb = *(const float4*)(g_enorm + e0 + 4);
    int ss[8] = {sa.x, sa.y, sa.z, sa.w, sb.x, sb.y, sb.z, sb.w};
    int dd[8] = {da.x, da.y, da.z, da.w, db.x, db.y, db.z, db.w};
    int rr[8] = {ra.x, ra.y, ra.z, ra.w, rb.x, rb.y, rb.z, rb.w};
    float nn[8] = {na.x, na.y, na.z, na.w, nb.x, nb.y, nb.z, nb.w};

    float4 tv[8];
#pragma unroll
    for (int k = 0; k < 8; k++) {
        tv[k] = *(const float4*)(g_T + (ss[k] * Rr + rr[k]) * Ll + half * 4);
    }
#pragma unroll
    for (int k = 0; k < 8; k++) {
        float4 v = make_float4(tv[k].x * nn[k], tv[k].y * nn[k],
                               tv[k].z * nn[k], tv[k].w * nn[k]);
        red_add_v4(&out[dd[k] * Ll + half * 4], v);
    }
}

// ---------------------------------------------------------------------------
// Final: out = sigmoid(out), elementwise
// ---------------------------------------------------------------------------
__global__ void k_final(float* __restrict__ out) {
    int i = blockIdx.x * blockDim.x + threadIdx.x;
    if (i >= (Nn * Ll) / 4) return;
    float4 v = ((const float4*)out)[i];
    v.x = 1.0f / (1.0f + expf(-v.x));
    v.y = 1.0f / (1.0f + expf(-v.y));
    v.z = 1.0f / (1.0f + expf(-v.z));
    v.w = 1.0f / (1.0f + expf(-v.w));
    ((float4*)out)[i] = v;
}

// ---------------------------------------------------------------------------
extern "C" void kernel_launch(void* const* d_in, const int* in_sizes, int n_in,
                              void* d_out, int out_size) {
    const int* ei    = (const int*)d_in[0];    // edge_index [2, E]
    const int* et    = (const int*)d_in[1];    // edge_type  [E]
    const float* W1  = (const float*)d_in[2];  // [R, N, H]
    const float* rt1 = (const float*)d_in[3];  // [N, H]
    const float* b1  = (const float*)d_in[4];  // [H]
    const float* W2  = (const float*)d_in[5];  // [R, H, L]
    const float* rt2 = (const float*)d_in[6];  // [H, L]
    const float* b2  = (const float*)d_in[7];  // [L]
    float* out = (float*)d_out;                // [N, L]

    const int* src = ei;
    const int* dst = ei + Ee;

    k_zero<<<1024, 256>>>();
    k_count<<<(Ee / 8 + 255) / 256, 256>>>(et, dst);
    k_layer1<<<(Ee / 4) * 8 / 256, 256>>>(src, dst, et, W1);     // 8 thr/edge, 4 edges/thr
    k_T<<<(Nn + 31) / 32, 256>>>(W2, rt1, b1, rt2, b2, out);     // register-weight GEMM
    k_layer2<<<((Ee / 8) * 2 + 255) / 256, 256>>>(src, dst, et, out); // 2 thr/edge, 8 edges/thr
    k_final<<<((Nn * Ll) / 4 + 255) / 256, 256>>>(out);
}